// round 13
// baseline (speedup 1.0000x reference)
#include <cuda_runtime.h>
#include <cuda_bf16.h>
#include <math.h>

#define B_  512
#define S_  128
#define F_  128
#define H_  512
#define H2_ 1024
#define G3_ 1536
#define KAUG 416  // 3*129 padded to /32

// ---------------- device scratch ----------------
__device__ float          g_h[B_*H_];
__device__ __nv_bfloat16  g_S[B_*H_];
__device__ __nv_bfloat16  g_a[B_*H2_];
__device__ __nv_bfloat16  g_w1b[H_*H2_];
__device__ __nv_bfloat16  g_w2b[H2_*H_];
__device__ __nv_bfloat16  g_Bp[G3_*G3_];            // [Whi;Whi;Wlo] (k,n) for gh
__device__ __nv_bfloat16  g_Ap[B_*G3_];             // [hi(h),lo(h),hi(h)]
__device__ float          g_gh[B_*G3_];
__device__ float          g_gi[(size_t)B_*S_*G3_];  // precomputed input gates
__device__ __nv_bfloat16  g_Ax[(size_t)B_*S_*KAUG];
__device__ __nv_bfloat16  g_Bx[KAUG*G3_];
__device__ float          g_sub[S_];
__device__ unsigned       g_barc[8];
__device__ unsigned       g_fa[8][16];   // a-tile epoch flags (per 64-col producer)
__device__ unsigned       g_fS[8][16];   // S-tile epoch flags (per 32-col producer)

__constant__ float c_next[6][6] = {
  {0.2f,0.f,0.f,0.f,0.f,0.f},
  {0.075f,0.225f,0.f,0.f,0.f,0.f},
  {(float)(44.0/45.0),(float)(-56.0/15.0),(float)(32.0/9.0),0.f,0.f,0.f},
  {(float)(19372.0/6561.0),(float)(-25360.0/2187.0),(float)(64448.0/6561.0),(float)(-212.0/729.0),0.f,0.f},
  {(float)(9017.0/3168.0),(float)(-355.0/33.0),(float)(46732.0/5247.0),(float)(49.0/176.0),(float)(-5103.0/18656.0),0.f},
  {(float)(35.0/384.0),0.f,(float)(500.0/1113.0),(float)(125.0/192.0),(float)(-2187.0/6784.0),(float)(11.0/84.0)}
};

// ---------------- fused prep ----------------
__global__ void k_pre(const float* __restrict__ tp, const float* __restrict__ vals,
                      const float* __restrict__ w1, const float* __restrict__ w2,
                      const float* __restrict__ whh, const float* __restrict__ wih){
  size_t i = (size_t)blockIdx.x*256 + threadIdx.x;
  if (i < (size_t)B_*S_*KAUG){
    int k = (int)(i % KAUG);
    size_t r = i / KAUG;
    int s = (int)(r % S_), b = (int)(r / S_);
    if (k >= 387){ g_Ax[i]=__float2bfloat16(0.f); }
    else {
      int j = (k<129) ? k : (k<258 ? k-129 : k-258);
      float x = (j < 128) ? vals[r*F_ + j]
                          : ((s==0) ? 0.f : (tp[b*S_+s]-tp[b*S_+s-1]));
      __nv_bfloat16 hi = __float2bfloat16(x);
      g_Ax[i] = (k<129 || k>=258) ? hi : __float2bfloat16(x - __bfloat162float(hi));
    }
  }
  if (i < (size_t)G3_*G3_){
    int n = (int)(i % G3_), k = (int)(i / G3_);
    int j = (k<H_) ? k : (k<2*H_ ? k-H_ : k-2*H_);
    float wv = whh[n*H_ + j];
    __nv_bfloat16 hi = __float2bfloat16(wv);
    g_Bp[i] = (k < 2*H_) ? hi : __float2bfloat16(wv - __bfloat162float(hi));
  }
  if (i < (size_t)KAUG*G3_){
    int n = (int)(i % G3_), k = (int)(i / G3_);
    if (k >= 387){ g_Bx[i]=__float2bfloat16(0.f); }
    else {
      int j = (k<129) ? k : (k<258 ? k-129 : k-258);
      float wv = wih[n*129 + j];
      __nv_bfloat16 hi = __float2bfloat16(wv);
      g_Bx[i] = (k < 258) ? hi : __float2bfloat16(wv - __bfloat162float(hi));
    }
  }
  if (i < (size_t)H_*H2_){
    g_w1b[i]=__float2bfloat16(w1[i]); g_w2b[i]=__float2bfloat16(w2[i]);
  }
  if (i < (size_t)B_*G3_) g_Ap[i]=__float2bfloat16(0.f);
  if (i < (size_t)B_*H_){ g_h[i]=0.f; g_S[i]=__float2bfloat16(0.f); }
  if (i < 8) g_barc[i]=0u;
  if (i < 128){ ((unsigned*)g_fa)[i]=0u; ((unsigned*)g_fS)[i]=0u; }
  if (i < S_){
    int s = (int)i; float a0=0.f, a1=0.f;
    for (int b=0;b<B_;b++){ a0 += tp[b*S_+s]; if (s>0) a1 += tp[b*S_+s-1]; }
    float dtm = (s==0) ? 0.f : (a0-a1)/(512.0f*72.0f);
    g_sub[s] = (dtm > 1e-4f) ? dtm/8.0f : 0.f;
  }
}

// ---------------- mma / sync helpers ----------------
__device__ __forceinline__ void mma_bf16(float* c, const unsigned* a, const unsigned* b){
  asm volatile(
    "mma.sync.aligned.m16n8k16.row.col.f32.bf16.bf16.f32 "
    "{%0,%1,%2,%3},{%4,%5,%6,%7},{%8,%9},{%0,%1,%2,%3};\n"
    : "+f"(c[0]), "+f"(c[1]), "+f"(c[2]), "+f"(c[3])
    : "r"(a[0]), "r"(a[1]), "r"(a[2]), "r"(a[3]), "r"(b[0]), "r"(b[1]));
}
__device__ __forceinline__ void ldsm4(unsigned* r, const __nv_bfloat16* p){
  unsigned a = (unsigned)__cvta_generic_to_shared(p);
  asm volatile("ldmatrix.sync.aligned.m8n8.x4.shared.b16 {%0,%1,%2,%3},[%4];\n"
    : "=r"(r[0]),"=r"(r[1]),"=r"(r[2]),"=r"(r[3]) : "r"(a));
}
__device__ __forceinline__ void ldsm4t(unsigned* r, const __nv_bfloat16* p){
  unsigned a = (unsigned)__cvta_generic_to_shared(p);
  asm volatile("ldmatrix.sync.aligned.m8n8.x4.trans.shared.b16 {%0,%1,%2,%3},[%4];\n"
    : "=r"(r[0]),"=r"(r[1]),"=r"(r[2]),"=r"(r[3]) : "r"(a));
}
__device__ __forceinline__ unsigned ldrlx(const unsigned* p){
  unsigned v; asm volatile("ld.relaxed.gpu.global.u32 %0,[%1];":"=r"(v):"l"(p):"memory"); return v;
}
__device__ __forceinline__ void strel(unsigned* p, unsigned v){
  asm volatile("st.release.gpu.global.u32 [%0],%1;"::"l"(p),"r"(v):"memory");
}
__device__ __forceinline__ void fence_acq(){
  asm volatile("fence.acq_rel.gpu;":::"memory");
}
// group barrier (step boundaries only): single-thread release/acquire poll.
__device__ __forceinline__ void gbar(unsigned* c, unsigned &gen){
  gen += 16;
  __syncthreads();
  if (threadIdx.x == 0){
    __threadfence();
    atomicAdd(c, 1u);
    unsigned v;
    do {
      asm volatile("ld.acquire.gpu.global.u32 %0,[%1];" : "=r"(v) : "l"(c) : "memory");
    } while (v < gen);
  }
  __syncthreads();
}

// ---- 64xTN GEMM, BK=128, flag-synchronized chunks, B resident in smem ----
// Chunk c covers A cols [c*128, c*128+128); flags[c*FPC .. c*FPC+FPC-1] guard it.
// t0-only polling: entry confirms chunks c0,c0+1 (relaxed spin + 1 acquire fence);
// chunk it+2's flags are issued relaxed before compute, checked after (latency hidden).
template<int TN, int FPC, int NIT>
__device__ __forceinline__ void gemm_flag(
    const __nv_bfloat16* __restrict__ A, int lda,
    const __nv_bfloat16* Ws, int wstr,
    __nv_bfloat16* As, float (&acc)[TN/16][4],
    unsigned* flags, unsigned ep, int c0)
{
  const int t=threadIdx.x, lane=t&31, w=t>>5;
  const int wm=(w>>1)*16;
  const int l8=lane&7, gq=lane>>3;
  if (t==0){
#pragma unroll
    for (int q=0;q<2;q++){
      int c = c0+q; if (c>=NIT) c-=NIT;
#pragma unroll
      for (int f=0;f<FPC;f++){
        const unsigned* fp = &flags[c*FPC + f];
        while (ldrlx(fp) < ep) __nanosleep(40);
      }
    }
    fence_acq();
  }
  __syncthreads();
  int cc = c0;
  uint4 pa[4];
#pragma unroll
  for (int i=0;i<4;i++)
    pa[i] = *(const uint4*)(A + (size_t)(t>>2)*lda + cc*128 + (t&3)*32 + i*8);
  int buf=0;
  for (int it=0; it<NIT; it++, buf^=1){
    __nv_bfloat16* Ab = As + buf*(64*136);
    {
      __nv_bfloat16* d = Ab + (t>>2)*136 + (t&3)*32;
#pragma unroll
      for (int i=0;i<4;i++) *(uint4*)(d + i*8) = pa[i];
    }
    __syncthreads();
    int cn = cc+1; if (cn>=NIT) cn-=NIT;
    if (it+1 < NIT){
#pragma unroll
      for (int i=0;i<4;i++)
        pa[i] = *(const uint4*)(A + (size_t)(t>>2)*lda + cn*128 + (t&3)*32 + i*8);
    }
    // issue lookahead flag loads (relaxed) for chunk it+2; check after compute
    unsigned vls[FPC]; int cl = -1;
    if (t==0 && it+2 < NIT){
      cl = cc+2; if (cl>=NIT) cl-=NIT;
#pragma unroll
      for (int f=0;f<FPC;f++) vls[f] = ldrlx(&flags[cl*FPC + f]);
    }
#pragma unroll
    for (int kk=0;kk<128;kk+=16){
      unsigned af[4];
      ldsm4(af, Ab + (wm+(lane&15))*136 + kk + ((lane>>4)<<3));
#pragma unroll
      for (int tn2=0;tn2<TN/32;tn2++){
        unsigned bfr[4];
        ldsm4t(bfr, Ws + (size_t)(cc*128+kk+l8+((gq&1)<<3))*wstr
                    + ((w&1)*(TN/2)) + tn2*16 + ((gq>>1)<<3));
#pragma unroll
        for (int h2=0;h2<2;h2++){
          unsigned bb[2] = { bfr[h2*2], bfr[h2*2+1] };
          mma_bf16(acc[tn2*2+h2], af, bb);
        }
      }
    }
    if (t==0 && cl >= 0){
#pragma unroll
      for (int f=0;f<FPC;f++){
        const unsigned* fp = &flags[cl*FPC + f];
        while (vls[f] < ep){ __nanosleep(40); vls[f] = ldrlx(fp); }
      }
      fence_acq();
    }
    cc = cn;
  }
}

// ---------------- persistent scan: 8 groups x 16 CTAs, 256 thr ----------------
__global__ void __launch_bounds__(256,1) k_scan(
  const float* __restrict__ b1, const float* __restrict__ b2,
  const float* __restrict__ bih, const float* __restrict__ bhh,
  const float* __restrict__ gamma, const float* __restrict__ beta,
  float* __restrict__ out)
{
  extern __shared__ __nv_bfloat16 sm[];
  __nv_bfloat16* Ws1 = sm;                 // 512*72   (73728 B)
  __nv_bfloat16* Ws2 = Ws1 + 512*72;       // 1024*40  (81920 B)
  __nv_bfloat16* As  = Ws2 + 1024*40;      // 2*64*136 (34816 B)
  __nv_bfloat16* Bs  = As  + 2*64*136;     // 2*64*40  (10240 B)   total 200704
  __shared__ float red2[16];

  const int t = threadIdx.x;
  const int g = blockIdx.x >> 4;
  const int cb = blockIdx.x & 15;
  const int lane = t&31, w = t>>5;
  const int wm = (w>>1)*16;
  const int qr = lane>>2, qc = lane&3;
  const int l8 = lane&7, gq = lane>>3;
  unsigned* barc = &g_barc[g];
  unsigned* fA = g_fa[g];
  unsigned* fS = g_fS[g];
  unsigned gen = 0, epA = 0, epS = 0;

  // resident weight slices
  for (int i=t;i<4096;i+=256){
    int r=i>>3, c8=i&7;
    *(uint4*)(Ws1 + r*72 + c8*8) = *(const uint4*)(g_w1b + (size_t)r*H2_ + cb*64 + c8*8);
  }
  for (int i=t;i<4096;i+=256){
    int r=i>>2, c8=i&3;
    *(uint4*)(Ws2 + r*40 + c8*8) = *(const uint4*)(g_w2b + (size_t)r*H_ + cb*32 + c8*8);
  }
  __syncthreads();

  const __nv_bfloat16* Sg  = g_S  + g*64*H_;
  const __nv_bfloat16* Ag  = g_a  + g*64*H2_;
  const __nv_bfloat16* Apg = g_Ap + (size_t)g*64*G3_;

  float hreg[8];     // RK45 h state (thread-owned epilogue elements)
  float kreg[5][8];  // k1..k5

  for (int s=0; s<S_; s++){
    float sub = g_sub[s];
    if (sub != 0.f){
      // refresh hreg from g_h (post-GRU); layout = GEMM2 epilogue mapping
#pragma unroll
      for (int tn=0;tn<2;tn++)
#pragma unroll
        for (int rh=0;rh<2;rh++){
          int rrg = g*64 + wm + qr + rh*8;
          int ccg = cb*32 + (w&1)*16 + tn*8 + qc*2;
          float2 v = *(const float2*)(g_h + (size_t)rrg*H_ + ccg);
          hreg[tn*4+rh*2+0]=v.x; hreg[tn*4+rh*2+1]=v.y;
        }

      for (int u=0; u<8; u++){
#pragma unroll
        for (int st=1; st<=6; st++){
          { // ---- GEMM1: a = tanh(S @ W1 + b1), 64x64, K=512, flag-synced ----
            float acc1[4][4];
#pragma unroll
            for (int j=0;j<4;j++)
#pragma unroll
              for (int e=0;e<4;e++) acc1[j][e]=0.f;
            gemm_flag<64,4,4>(Sg, H_, Ws1, 72, As, acc1, fS, epS, cb>>2);
            const int wn = (w&1)*32;
#pragma unroll
            for (int tn=0;tn<4;tn++){
              int ccg = cb*64 + wn + tn*8 + qc*2;
              float bb0 = b1[ccg], bb1 = b1[ccg+1];
#pragma unroll
              for (int rh=0;rh<2;rh++){
                int rrg = g*64 + wm + qr + rh*8;
                __nv_bfloat162 v2;
                v2.x = __float2bfloat16(tanhf(acc1[tn][rh*2+0] + bb0));
                v2.y = __float2bfloat16(tanhf(acc1[tn][rh*2+1] + bb1));
                *(__nv_bfloat162*)(g_a + (size_t)rrg*H2_ + ccg) = v2;
              }
            }
            __syncthreads();
            epA++;
            if (t==0){ __threadfence(); strel(&fA[cb], epA); }
          }
          { // ---- GEMM2: k = a @ W2 + b2, 64x32, K=1024, flag-synced ----
            float acc2[2][4];
#pragma unroll
            for (int j=0;j<2;j++)
#pragma unroll
              for (int e=0;e<4;e++) acc2[j][e]=0.f;
            gemm_flag<32,2,8>(Ag, H2_, Ws2, 40, As, acc2, fA, epA, cb>>1);
            // RK45 epilogue with register k/h state
            const int wn = (w&1)*16;
            bool last = (st==6) && (u==7);
#pragma unroll
            for (int tn=0;tn<2;tn++){
              int cl0 = wn + tn*8 + qc*2;
              int ccg = cb*32 + cl0;
              float bb0 = b2[ccg], bb1 = b2[ccg+1];
#pragma unroll
              for (int rh=0;rh<2;rh++){
                int rrg = g*64 + wm + qr + rh*8;
                float sv[2];
#pragma unroll
                for (int e2=0;e2<2;e2++){
                  int r = tn*4 + rh*2 + e2;
                  float kv = acc2[tn][rh*2+e2] + (e2 ? bb1 : bb0);
                  if (st < 6) kreg[st-1][r] = kv;
                  float sum = c_next[st-1][st-1]*kv;
#pragma unroll
                  for (int j=0;j<5;j++)
                    if (j < st-1) sum += c_next[st-1][j]*kreg[j][r];
                  float s2 = hreg[r] + sub*sum;
                  if (st == 6) hreg[r] = s2;
                  sv[e2] = s2;
                }
                if (last){
                  *(float2*)(g_h + (size_t)rrg*H_ + ccg) = make_float2(sv[0], sv[1]);
                  __nv_bfloat162 hi2, lo2;
                  hi2.x = __float2bfloat16(sv[0]);
                  hi2.y = __float2bfloat16(sv[1]);
                  lo2.x = __float2bfloat16(sv[0] - __bfloat162float(hi2.x));
                  lo2.y = __float2bfloat16(sv[1] - __bfloat162float(hi2.y));
                  *(__nv_bfloat162*)(g_Ap + (size_t)rrg*G3_ + ccg)        = hi2;
                  *(__nv_bfloat162*)(g_Ap + (size_t)rrg*G3_ + H_ + ccg)   = lo2;
                  *(__nv_bfloat162*)(g_Ap + (size_t)rrg*G3_ + 2*H_ + ccg) = hi2;
                } else {
                  __nv_bfloat162 s2v;
                  s2v.x = __float2bfloat16(sv[0]);
                  s2v.y = __float2bfloat16(sv[1]);
                  *(__nv_bfloat162*)(g_S + (size_t)rrg*H_ + ccg) = s2v;
                }
              }
            }
            __syncthreads();
            epS++;
            if (t==0){ __threadfence(); strel(&fS[cb], epS); }
          }
        }
      }
    }
    gbar(barc, gen);   // Ap/S writes globally visible before gh
    // ---- gh GEMM: 3 tiles of 64x32, K=1536, BK=64 (24 iters), streamed B ----
    for (int it3=0; it3<3; it3++){
      float acc2[2][4];
#pragma unroll
      for (int j=0;j<2;j++)
#pragma unroll
        for (int e=0;e<4;e++) acc2[j][e]=0.f;
      int n0 = cb*96 + it3*32;
      uint4 pa0, pa1, pb;
      { const __nv_bfloat16* p = Apg + (size_t)(t>>2)*G3_ + (t&3)*16;
        pa0 = *(const uint4*)p; pa1 = *(const uint4*)(p+8);
        pb = *(const uint4*)(g_Bp + (size_t)(t>>2)*G3_ + n0 + (t&3)*8); }
      int buf = 0;
      for (int c=0;c<24;c++,buf^=1){
        __nv_bfloat16* Ab = As + buf*(64*136);
        __nv_bfloat16* Bb = Bs + buf*(64*40);
        { __nv_bfloat16* d = Ab + (t>>2)*72 + (t&3)*16;
          *(uint4*)d = pa0; *(uint4*)(d+8) = pa1; }
        *(uint4*)(Bb + (t>>2)*40 + (t&3)*8) = pb;
        __syncthreads();
        if (c<23){
          const __nv_bfloat16* p = Apg + (size_t)(t>>2)*G3_ + (c+1)*64 + (t&3)*16;
          pa0 = *(const uint4*)p; pa1 = *(const uint4*)(p+8);
          pb = *(const uint4*)(g_Bp + (size_t)((c+1)*64 + (t>>2))*G3_ + n0 + (t&3)*8);
        }
#pragma unroll
        for (int kk=0;kk<64;kk+=16){
          unsigned af[4];
          ldsm4(af, Ab + (wm+(lane&15))*72 + kk + ((lane>>4)<<3));
          unsigned bfr[4];
          ldsm4t(bfr, Bb + (kk+l8+((gq&1)<<3))*40 + ((w&1)<<4) + ((gq>>1)<<3));
#pragma unroll
          for (int h2=0;h2<2;h2++){
            unsigned bb[2] = { bfr[h2*2], bfr[h2*2+1] };
            mma_bf16(acc2[h2], af, bb);
          }
        }
      }
      const int wn = (w&1)*16;
#pragma unroll
      for (int tn=0;tn<2;tn++){
        int ccg = n0 + wn + tn*8 + qc*2;
#pragma unroll
        for (int rh=0;rh<2;rh++){
          int rrg = g*64 + wm + qr + rh*8;
          *(float2*)(g_gh + (size_t)rrg*G3_ + ccg) =
              make_float2(acc2[tn][rh*2+0], acc2[tn][rh*2+1]);
        }
      }
    }
    gbar(barc, gen);
    { // ---- GRU + LayerNorm ----
      int b = g*64 + cb*4 + (w>>1);
      int half = w&1;
      const float* gi = g_gi + ((size_t)b*S_ + s)*G3_;
      const float* gh = g_gh + (size_t)b*G3_;
      float v[8]; float lsum = 0.f;
#pragma unroll
      for (int jj=0;jj<8;jj++){
        int j = half*256 + lane + jj*32;
        float rg = 1.f/(1.f+expf(-(gi[j]      + bih[j]      + gh[j]      + bhh[j])));
        float zg = 1.f/(1.f+expf(-(gi[j+H_]   + bih[j+H_]   + gh[j+H_]   + bhh[j+H_])));
        float ng = tanhf(gi[j+2*H_] + bih[j+2*H_] + rg*(gh[j+2*H_] + bhh[j+2*H_]));
        float hv = (1.f - zg)*ng + zg*g_h[(size_t)b*H_+j];
        v[jj] = hv; lsum += hv;
      }
#pragma unroll
      for (int jj=0;jj<8;jj++){
        int j = half*256 + lane + jj*32; float hv = v[jj];
        g_h[(size_t)b*H_+j] = hv;
        g_S[(size_t)b*H_+j] = __float2bfloat16(hv);
        __nv_bfloat16 hi = __float2bfloat16(hv);
        __nv_bfloat16 lo = __float2bfloat16(hv - __bfloat162float(hi));
        g_Ap[(size_t)b*G3_ + j]        = hi;
        g_Ap[(size_t)b*G3_ + H_ + j]   = lo;
        g_Ap[(size_t)b*G3_ + 2*H_ + j] = hi;
      }
#pragma unroll
      for (int o=16;o>0;o>>=1) lsum += __shfl_xor_sync(0xffffffffu, lsum, o);
      if (lane==0) red2[w] = lsum;
      __syncthreads();
      float mu = (red2[w & ~1] + red2[w | 1]) / 512.f;
      float lvar = 0.f;
#pragma unroll
      for (int jj=0;jj<8;jj++){ float d = v[jj]-mu; lvar += d*d; }
#pragma unroll
      for (int o=16;o>0;o>>=1) lvar += __shfl_xor_sync(0xffffffffu, lvar, o);
      if (lane==0) red2[8+w] = lvar;
      __syncthreads();
      float inv = rsqrtf((red2[8+(w & ~1)] + red2[8+(w | 1)])/512.f + 1e-5f);
      float* op = out + ((size_t)b*S_ + s)*H_;
#pragma unroll
      for (int jj=0;jj<8;jj++){
        int j = half*256 + lane + jj*32;
        op[j] = (v[jj]-mu)*inv*gamma[j] + beta[j];
      }
    }
    gbar(barc, gen);
  }
}

// ---------------- one-time gi GEMM (64x64 tile, 128 thr) ----------------
__global__ void __launch_bounds__(128) k_gi(){
  __shared__ __nv_bfloat16 As[64*40];
  __shared__ __nv_bfloat16 Bsl[32*72];
  const int t = threadIdx.x;
  const int m0 = blockIdx.y*64, n0 = blockIdx.x*64;
  const int lane = t&31, w = t>>5;
  const int wm = (w>>1)*32, wn = (w&1)*32;
  const int qr = lane>>2, qc = lane&3;
  float acc[2][4][4];
#pragma unroll
  for (int i=0;i<2;i++)
#pragma unroll
    for (int j=0;j<4;j++)
#pragma unroll
      for (int e=0;e<4;e++) acc[i][j][e]=0.f;
  uint4 pa[2], pb[2];
#pragma unroll
  for (int i=0;i<2;i++){
    int cI = t + i*128;
    pa[i] = *(const uint4*)(g_Ax + (size_t)(m0 + (cI>>2))*KAUG + (cI&3)*8);
    pb[i] = *(const uint4*)(g_Bx + (size_t)(cI>>3)*G3_ + n0 + (cI&7)*8);
  }
  for (int k0=0; k0<KAUG; k0+=32){
#pragma unroll
    for (int i=0;i<2;i++){
      int cI = t + i*128;
      *(uint4*)(As + (cI>>2)*40 + (cI&3)*8) = pa[i];
      *(uint4*)(Bsl + (cI>>3)*72 + (cI&7)*8) = pb[i];
    }
    __syncthreads();
    if (k0+32 < KAUG){
#pragma unroll
      for (int i=0;i<2;i++){
        int cI = t + i*128;
        pa[i] = *(const uint4*)(g_Ax + (size_t)(m0 + (cI>>2))*KAUG + (k0+32) + (cI&3)*8);
        pb[i] = *(const uint4*)(g_Bx + (size_t)(k0+32 + (cI>>3))*G3_ + n0 + (cI&7)*8);
      }
    }
    int l8 = lane&7, gq = lane>>3;
#pragma unroll
    for (int kk=0; kk<32; kk+=16){
      unsigned af[2][4];
#pragma unroll
      for (int tm=0;tm<2;tm++)
        ldsm4(af[tm], As + (wm+tm*16+(lane&15))*40 + kk + ((lane>>4)<<3));
#pragma unroll
      for (int tn2=0; tn2<2; tn2++){
        unsigned bfr[4];
        ldsm4t(bfr, Bsl + (kk+l8+((gq&1)<<3))*72 + wn + tn2*16 + ((gq>>1)<<3));
#pragma unroll
        for (int tm=0;tm<2;tm++)
#pragma unroll
          for (int h2=0; h2<2; h2++){
            unsigned bb[2] = { bfr[h2*2], bfr[h2*2+1] };
            mma_bf16(acc[tm][tn2*2+h2], af[tm], bb);
          }
      }
    }
    __syncthreads();
  }
#pragma unroll
  for (int tm=0;tm<2;tm++)
#pragma unroll
    for (int tn=0;tn<4;tn++){
      int r0 = m0 + wm + tm*16 + qr;
      int c0 = n0 + wn + tn*8 + qc*2;
#pragma unroll
      for (int e=0;e<4;e++){
        int rr = r0 + (e>>1)*8, cc = c0 + (e&1);
        g_gi[(size_t)rr*G3_ + cc] = acc[tm][tn][e];
      }
    }
}

// ---------------- host ----------------
extern "C" void kernel_launch(void* const* d_in, const int* in_sizes, int n_in,
                              void* d_out, int out_size){
  const float* tp    = (const float*)d_in[0];
  const float* vals  = (const float*)d_in[1];
  const float* w1    = (const float*)d_in[2];
  const float* b1    = (const float*)d_in[3];
  const float* w2    = (const float*)d_in[4];
  const float* b2    = (const float*)d_in[5];
  const float* wih   = (const float*)d_in[6];
  const float* whh   = (const float*)d_in[7];
  const float* bih   = (const float*)d_in[8];
  const float* bhh   = (const float*)d_in[9];
  const float* gamma = (const float*)d_in[10];
  const float* beta  = (const float*)d_in[11];
  float* out = (float*)d_out;
  (void)in_sizes; (void)n_in; (void)out_size;

  const int SMEM = 512*72*2 + 1024*40*2 + 2*64*136*2 + 2*64*40*2; // 200704 B
  cudaFuncSetAttribute(k_scan, cudaFuncAttributeMaxDynamicSharedMemorySize, SMEM);

  {
    size_t n = (size_t)B_*S_*KAUG;
    k_pre<<<(unsigned)((n+255)/256),256>>>(tp, vals, w1, w2, whh, wih);
  }
  k_gi<<<dim3(G3_/64,(B_*S_)/64),128>>>();
  k_scan<<<128,256,SMEM>>>(b1,b2,bih,bhh,gamma,beta,out);
}

// round 14
// speedup vs baseline: 2.6627x; 2.6627x over previous
#include <cuda_runtime.h>
#include <cuda_bf16.h>
#include <math.h>

#define B_  512
#define S_  128
#define F_  128
#define H_  512
#define H2_ 1024
#define G3_ 1536
#define KAUG 416  // 3*129 padded to /32

// ---------------- device scratch ----------------
__device__ float          g_h[B_*H_];
__device__ __nv_bfloat16  g_S[B_*H_];
__device__ __nv_bfloat16  g_a[B_*H2_];
__device__ __nv_bfloat16  g_w1b[H_*H2_];
__device__ __nv_bfloat16  g_w2b[H2_*H_];
__device__ __nv_bfloat16  g_Bp[G3_*G3_];            // [Whi;Whi;Wlo] (k,n) for gh
__device__ __nv_bfloat16  g_Ap[B_*G3_];             // [hi(h),lo(h),hi(h)]
__device__ float          g_gh[B_*G3_];
__device__ float          g_gi[(size_t)B_*S_*G3_];  // precomputed input gates
__device__ __nv_bfloat16  g_Ax[(size_t)B_*S_*KAUG];
__device__ __nv_bfloat16  g_Bx[KAUG*G3_];
__device__ float          g_sub[S_];
__device__ unsigned       g_barc[8];

__constant__ float c_next[6][6] = {
  {0.2f,0.f,0.f,0.f,0.f,0.f},
  {0.075f,0.225f,0.f,0.f,0.f,0.f},
  {(float)(44.0/45.0),(float)(-56.0/15.0),(float)(32.0/9.0),0.f,0.f,0.f},
  {(float)(19372.0/6561.0),(float)(-25360.0/2187.0),(float)(64448.0/6561.0),(float)(-212.0/729.0),0.f,0.f},
  {(float)(9017.0/3168.0),(float)(-355.0/33.0),(float)(46732.0/5247.0),(float)(49.0/176.0),(float)(-5103.0/18656.0),0.f},
  {(float)(35.0/384.0),0.f,(float)(500.0/1113.0),(float)(125.0/192.0),(float)(-2187.0/6784.0),(float)(11.0/84.0)}
};

// ---------------- fused prep ----------------
__global__ void k_pre(const float* __restrict__ tp, const float* __restrict__ vals,
                      const float* __restrict__ w1, const float* __restrict__ w2,
                      const float* __restrict__ whh, const float* __restrict__ wih){
  size_t i = (size_t)blockIdx.x*256 + threadIdx.x;
  if (i < (size_t)B_*S_*KAUG){
    int k = (int)(i % KAUG);
    size_t r = i / KAUG;
    int s = (int)(r % S_), b = (int)(r / S_);
    if (k >= 387){ g_Ax[i]=__float2bfloat16(0.f); }
    else {
      int j = (k<129) ? k : (k<258 ? k-129 : k-258);
      float x = (j < 128) ? vals[r*F_ + j]
                          : ((s==0) ? 0.f : (tp[b*S_+s]-tp[b*S_+s-1]));
      __nv_bfloat16 hi = __float2bfloat16(x);
      g_Ax[i] = (k<129 || k>=258) ? hi : __float2bfloat16(x - __bfloat162float(hi));
    }
  }
  if (i < (size_t)G3_*G3_){
    int n = (int)(i % G3_), k = (int)(i / G3_);
    int j = (k<H_) ? k : (k<2*H_ ? k-H_ : k-2*H_);
    float wv = whh[n*H_ + j];
    __nv_bfloat16 hi = __float2bfloat16(wv);
    g_Bp[i] = (k < 2*H_) ? hi : __float2bfloat16(wv - __bfloat162float(hi));
  }
  if (i < (size_t)KAUG*G3_){
    int n = (int)(i % G3_), k = (int)(i / G3_);
    if (k >= 387){ g_Bx[i]=__float2bfloat16(0.f); }
    else {
      int j = (k<129) ? k : (k<258 ? k-129 : k-258);
      float wv = wih[n*129 + j];
      __nv_bfloat16 hi = __float2bfloat16(wv);
      g_Bx[i] = (k < 258) ? hi : __float2bfloat16(wv - __bfloat162float(hi));
    }
  }
  if (i < (size_t)H_*H2_){
    g_w1b[i]=__float2bfloat16(w1[i]); g_w2b[i]=__float2bfloat16(w2[i]);
  }
  if (i < (size_t)B_*G3_) g_Ap[i]=__float2bfloat16(0.f);
  if (i < (size_t)B_*H_){ g_h[i]=0.f; g_S[i]=__float2bfloat16(0.f); }
  if (i < 8) g_barc[i]=0u;
  if (i < S_){
    int s = (int)i; float a0=0.f, a1=0.f;
    for (int b=0;b<B_;b++){ a0 += tp[b*S_+s]; if (s>0) a1 += tp[b*S_+s-1]; }
    float dtm = (s==0) ? 0.f : (a0-a1)/(512.0f*72.0f);
    g_sub[s] = (dtm > 1e-4f) ? dtm/8.0f : 0.f;
  }
}

// ---------------- mma / sync helpers ----------------
__device__ __forceinline__ void mma_bf16(float* c, const unsigned* a, const unsigned* b){
  asm volatile(
    "mma.sync.aligned.m16n8k16.row.col.f32.bf16.bf16.f32 "
    "{%0,%1,%2,%3},{%4,%5,%6,%7},{%8,%9},{%0,%1,%2,%3};\n"
    : "+f"(c[0]), "+f"(c[1]), "+f"(c[2]), "+f"(c[3])
    : "r"(a[0]), "r"(a[1]), "r"(a[2]), "r"(a[3]), "r"(b[0]), "r"(b[1]));
}
__device__ __forceinline__ void ldsm4(unsigned* r, const __nv_bfloat16* p){
  unsigned a = (unsigned)__cvta_generic_to_shared(p);
  asm volatile("ldmatrix.sync.aligned.m8n8.x4.shared.b16 {%0,%1,%2,%3},[%4];\n"
    : "=r"(r[0]),"=r"(r[1]),"=r"(r[2]),"=r"(r[3]) : "r"(a));
}
__device__ __forceinline__ void ldsm4t(unsigned* r, const __nv_bfloat16* p){
  unsigned a = (unsigned)__cvta_generic_to_shared(p);
  asm volatile("ldmatrix.sync.aligned.m8n8.x4.trans.shared.b16 {%0,%1,%2,%3},[%4];\n"
    : "=r"(r[0]),"=r"(r[1]),"=r"(r[2]),"=r"(r[3]) : "r"(a));
}
// split group barrier on a single counter (proven protocol, t0-only traffic).
// 16 CTAs/group, grid=128 @ 1 CTA/SM => single wave, no deadlock.
__device__ __forceinline__ void garr(unsigned* c, unsigned &gen){
  gen += 16;
  __syncthreads();
  if (threadIdx.x == 0){ __threadfence(); atomicAdd(c, 1u); }
}
__device__ __forceinline__ void gwait(unsigned* c, unsigned gen){
  if (threadIdx.x == 0){
    unsigned v;
    do {
      asm volatile("ld.acquire.gpu.global.u32 %0,[%1];" : "=r"(v) : "l"(c) : "memory");
    } while (v < gen);
  }
  __syncthreads();
}
__device__ __forceinline__ void gbar(unsigned* c, unsigned &gen){
  garr(c, gen); gwait(c, gen);
}

// ---- 64xTN GEMM, BK=128, full K from 0 (first stage of a step) ----
template<int TN>
__device__ __forceinline__ void gemm_bk128(
    const __nv_bfloat16* __restrict__ A, int lda, int K,
    const __nv_bfloat16* Ws, int wstr,
    __nv_bfloat16* As, float (&acc)[TN/16][4])
{
  const int t=threadIdx.x, lane=t&31, w=t>>5;
  const int wm=(w>>1)*16;
  const int l8=lane&7, gq=lane>>3;
  uint4 pa[4];
#pragma unroll
  for (int i=0;i<4;i++)
    pa[i] = *(const uint4*)(A + (size_t)(t>>2)*lda + (t&3)*32 + i*8);
  int buf=0;
  const int NIT = K/128;
  for (int it=0; it<NIT; it++, buf^=1){
    __nv_bfloat16* Ab = As + buf*(64*136);
    {
      __nv_bfloat16* d = Ab + (t>>2)*136 + (t&3)*32;
#pragma unroll
      for (int i=0;i<4;i++) *(uint4*)(d + i*8) = pa[i];
    }
    __syncthreads();
    if (it+1 < NIT){
#pragma unroll
      for (int i=0;i<4;i++)
        pa[i] = *(const uint4*)(A + (size_t)(t>>2)*lda + (it+1)*128 + (t&3)*32 + i*8);
    }
#pragma unroll
    for (int kk=0;kk<128;kk+=16){
      unsigned af[4];
      ldsm4(af, Ab + (wm+(lane&15))*136 + kk + ((lane>>4)<<3));
#pragma unroll
      for (int tn2=0;tn2<TN/32;tn2++){
        unsigned bfr[4];
        ldsm4t(bfr, Ws + (size_t)(it*128+kk+l8+((gq&1)<<3))*wstr
                    + ((w&1)*(TN/2)) + tn2*16 + ((gq>>1)<<3));
#pragma unroll
        for (int h2=0;h2<2;h2++){
          unsigned bb[2] = { bfr[h2*2], bfr[h2*2+1] };
          mma_bf16(acc[tn2*2+h2], af, bb);
        }
      }
    }
  }
}

// ---- remaining-K GEMM after self chunk: BK=128 chunks, wrapped, last capped ----
template<int TN, int MASK, int NIT, int LASTK>
__device__ __forceinline__ void gemm_rest(
    const __nv_bfloat16* __restrict__ A, int lda,
    const __nv_bfloat16* Ws, int wstr,
    __nv_bfloat16* As, float (&acc)[TN/16][4], int base0)
{
  const int t=threadIdx.x, lane=t&31, w=t>>5;
  const int wm=(w>>1)*16;
  const int l8=lane&7, gq=lane>>3;
  uint4 pa[4];
#pragma unroll
  for (int i=0;i<4;i++)
    pa[i] = *(const uint4*)(A + (size_t)(t>>2)*lda + ((base0 + (t&3)*32 + i*8) & MASK));
  int buf=0;
  for (int it=0; it<NIT; it++, buf^=1){
    const int base = (base0 + it*128) & MASK;
    __nv_bfloat16* Ab = As + buf*(64*136);
    {
      __nv_bfloat16* d = Ab + (t>>2)*136 + (t&3)*32;
#pragma unroll
      for (int i=0;i<4;i++) *(uint4*)(d + i*8) = pa[i];
    }
    __syncthreads();
    if (it+1 < NIT){
      const int bn = base0 + (it+1)*128;
#pragma unroll
      for (int i=0;i<4;i++)
        pa[i] = *(const uint4*)(A + (size_t)(t>>2)*lda + ((bn + (t&3)*32 + i*8) & MASK));
    }
    const bool lastit = (it == NIT-1);
#pragma unroll
    for (int kk=0;kk<128;kk+=16){
      if (kk < LASTK || !lastit){
        unsigned af[4];
        ldsm4(af, Ab + (wm+(lane&15))*136 + kk + ((lane>>4)<<3));
#pragma unroll
        for (int tn2=0;tn2<TN/32;tn2++){
          unsigned bfr[4];
          ldsm4t(bfr, Ws + (size_t)((base+kk+l8+((gq&1)<<3)) & MASK)*wstr
                      + ((w&1)*(TN/2)) + tn2*16 + ((gq>>1)<<3));
#pragma unroll
          for (int h2=0;h2<2;h2++){
            unsigned bb[2] = { bfr[h2*2], bfr[h2*2+1] };
            mma_bf16(acc[tn2*2+h2], af, bb);
          }
        }
      }
    }
  }
}

// ---- self chunks: data staged into smem by this CTA's own epilogue ----
__device__ __forceinline__ void gemm1_self(
    const __nv_bfloat16* Ws1, const __nv_bfloat16* As, float (&acc)[4][4], int cb)
{
  const int t=threadIdx.x, lane=t&31, w=t>>5;
  const int wm=(w>>1)*16, l8=lane&7, gq=lane>>3;
#pragma unroll
  for (int kk=0;kk<32;kk+=16){
    unsigned af[4];
    ldsm4(af, As + (wm+(lane&15))*40 + kk + ((lane>>4)<<3));
#pragma unroll
    for (int tn2=0;tn2<2;tn2++){
      unsigned bfr[4];
      ldsm4t(bfr, Ws1 + (size_t)(cb*32 + kk + l8 + ((gq&1)<<3))*72
                  + ((w&1)*32) + tn2*16 + ((gq>>1)<<3));
#pragma unroll
      for (int h2=0;h2<2;h2++){
        unsigned bb[2] = { bfr[h2*2], bfr[h2*2+1] };
        mma_bf16(acc[tn2*2+h2], af, bb);
      }
    }
  }
}
__device__ __forceinline__ void gemm2_self(
    const __nv_bfloat16* Ws2, const __nv_bfloat16* As, float (&acc)[2][4], int cb)
{
  const int t=threadIdx.x, lane=t&31, w=t>>5;
  const int wm=(w>>1)*16, l8=lane&7, gq=lane>>3;
#pragma unroll
  for (int kk=0;kk<64;kk+=16){
    unsigned af[4];
    ldsm4(af, As + (wm+(lane&15))*72 + kk + ((lane>>4)<<3));
    unsigned bfr[4];
    ldsm4t(bfr, Ws2 + (size_t)(cb*64 + kk + l8 + ((gq&1)<<3))*40
                + ((w&1)*16) + ((gq>>1)<<3));
#pragma unroll
    for (int h2=0;h2<2;h2++){
      unsigned bb[2] = { bfr[h2*2], bfr[h2*2+1] };
      mma_bf16(acc[h2], af, bb);
    }
  }
}

// ---------------- persistent scan: 8 groups x 16 CTAs, 256 thr ----------------
__global__ void __launch_bounds__(256,1) k_scan(
  const float* __restrict__ b1, const float* __restrict__ b2,
  const float* __restrict__ bih, const float* __restrict__ bhh,
  const float* __restrict__ gamma, const float* __restrict__ beta,
  float* __restrict__ out)
{
  extern __shared__ __nv_bfloat16 sm[];
  __nv_bfloat16* Ws1 = sm;                 // 512*72   (73728 B)
  __nv_bfloat16* Ws2 = Ws1 + 512*72;       // 1024*40  (81920 B)
  __nv_bfloat16* As  = Ws2 + 1024*40;      // 2*64*136 (34816 B)
  __nv_bfloat16* Bs  = As  + 2*64*136;     // 2*64*40  (10240 B)   total 200704
  __shared__ float red2[16];

  const int t = threadIdx.x;
  const int g = blockIdx.x >> 4;
  const int cb = blockIdx.x & 15;
  const int lane = t&31, w = t>>5;
  const int wm = (w>>1)*16;
  const int qr = lane>>2, qc = lane&3;
  const int l8 = lane&7, gq = lane>>3;
  unsigned* barc = &g_barc[g];
  unsigned gen = 0;

  // resident weight slices
  for (int i=t;i<4096;i+=256){
    int r=i>>3, c8=i&7;
    *(uint4*)(Ws1 + r*72 + c8*8) = *(const uint4*)(g_w1b + (size_t)r*H2_ + cb*64 + c8*8);
  }
  for (int i=t;i<4096;i+=256){
    int r=i>>2, c8=i&3;
    *(uint4*)(Ws2 + r*40 + c8*8) = *(const uint4*)(g_w2b + (size_t)r*H_ + cb*32 + c8*8);
  }
  __syncthreads();

  const __nv_bfloat16* Sg  = g_S  + g*64*H_;
  const __nv_bfloat16* Ag  = g_a  + g*64*H2_;
  const __nv_bfloat16* Apg = g_Ap + (size_t)g*64*G3_;

  float hreg[8];     // RK45 h state (thread-owned epilogue elements)
  float kreg[5][8];  // k1..k5

  for (int s=0; s<S_; s++){
    float sub = g_sub[s];
    if (sub != 0.f){
      // refresh hreg from g_h (post-GRU); layout = GEMM2 epilogue mapping
#pragma unroll
      for (int tn=0;tn<2;tn++)
#pragma unroll
        for (int rh=0;rh<2;rh++){
          int rrg = g*64 + wm + qr + rh*8;
          int ccg = cb*32 + (w&1)*16 + tn*8 + qc*2;
          float2 v = *(const float2*)(g_h + (size_t)rrg*H_ + ccg);
          hreg[tn*4+rh*2+0]=v.x; hreg[tn*4+rh*2+1]=v.y;
        }

      for (int u=0; u<8; u++){
#pragma unroll
        for (int st=1; st<=6; st++){
          { // ---- GEMM1: a = tanh(S @ W1 + b1), 64x64, K=512 ----
            float acc1[4][4];
#pragma unroll
            for (int j=0;j<4;j++)
#pragma unroll
              for (int e=0;e<4;e++) acc1[j][e]=0.f;
            if (st==1 && u==0){
              // first stage of step: post-GRU gbar already synced g_S
              gemm_bk128<64>(Sg, H_, H_, Ws1, 72, As, acc1);
            } else {
              gemm1_self(Ws1, As, acc1, cb);       // own 32 S-cols (staged)
              gwait(barc, gen);                    // others' S visible
              gemm_rest<64,511,4,96>(Sg, H_, Ws1, 72, As, acc1, cb*32+32);
            }
            const int wn = (w&1)*32;
#pragma unroll
            for (int tn=0;tn<4;tn++){
              int lcol = wn + tn*8 + qc*2;
              int ccg = cb*64 + lcol;
              float bb0 = b1[ccg], bb1 = b1[ccg+1];
#pragma unroll
              for (int rh=0;rh<2;rh++){
                int lrow = wm + qr + rh*8;
                int rrg = g*64 + lrow;
                __nv_bfloat162 v2;
                v2.x = __float2bfloat16(tanhf(acc1[tn][rh*2+0] + bb0));
                v2.y = __float2bfloat16(tanhf(acc1[tn][rh*2+1] + bb1));
                *(__nv_bfloat162*)(g_a + (size_t)rrg*H2_ + ccg) = v2;
                *(__nv_bfloat162*)(As + lrow*72 + lcol) = v2;   // stage self a
              }
            }
          }
          garr(barc, gen);
          { // ---- GEMM2: k = a @ W2 + b2, 64x32, K=1024 ----
            float acc2[2][4];
#pragma unroll
            for (int j=0;j<2;j++)
#pragma unroll
              for (int e=0;e<4;e++) acc2[j][e]=0.f;
            gemm2_self(Ws2, As, acc2, cb);         // own 64 a-cols (staged)
            gwait(barc, gen);                      // others' a visible
            gemm_rest<32,1023,8,64>(Ag, H2_, Ws2, 40, As, acc2, cb*64+64);
            // RK45 epilogue with register k/h state
            const int wn = (w&1)*16;
            bool last = (st==6) && (u==7);
#pragma unroll
            for (int tn=0;tn<2;tn++){
              int cl0 = wn + tn*8 + qc*2;
              int ccg = cb*32 + cl0;
              float bb0 = b2[ccg], bb1 = b2[ccg+1];
#pragma unroll
              for (int rh=0;rh<2;rh++){
                int lrow = wm + qr + rh*8;
                int rrg = g*64 + lrow;
                float sv[2];
#pragma unroll
                for (int e2=0;e2<2;e2++){
                  int r = tn*4 + rh*2 + e2;
                  float kv = acc2[tn][rh*2+e2] + (e2 ? bb1 : bb0);
                  if (st < 6) kreg[st-1][r] = kv;
                  float sum = c_next[st-1][st-1]*kv;
#pragma unroll
                  for (int j=0;j<5;j++)
                    if (j < st-1) sum += c_next[st-1][j]*kreg[j][r];
                  float s2 = hreg[r] + sub*sum;
                  if (st == 6) hreg[r] = s2;
                  sv[e2] = s2;
                }
                if (last){
                  *(float2*)(g_h + (size_t)rrg*H_ + ccg) = make_float2(sv[0], sv[1]);
                  __nv_bfloat162 hi2, lo2;
                  hi2.x = __float2bfloat16(sv[0]);
                  hi2.y = __float2bfloat16(sv[1]);
                  lo2.x = __float2bfloat16(sv[0] - __bfloat162float(hi2.x));
                  lo2.y = __float2bfloat16(sv[1] - __bfloat162float(hi2.y));
                  *(__nv_bfloat162*)(g_Ap + (size_t)rrg*G3_ + ccg)        = hi2;
                  *(__nv_bfloat162*)(g_Ap + (size_t)rrg*G3_ + H_ + ccg)   = lo2;
                  *(__nv_bfloat162*)(g_Ap + (size_t)rrg*G3_ + 2*H_ + ccg) = hi2;
                } else {
                  __nv_bfloat162 s2v;
                  s2v.x = __float2bfloat16(sv[0]);
                  s2v.y = __float2bfloat16(sv[1]);
                  *(__nv_bfloat162*)(g_S + (size_t)rrg*H_ + ccg) = s2v;
                  *(__nv_bfloat162*)(As + lrow*40 + cl0) = s2v;  // stage self S
                }
              }
            }
          }
          garr(barc, gen);
        }
      }
      gwait(barc, gen);   // consume final garr: all Ap/S visible before gh
    }
    // ---- gh GEMM: 3 tiles of 64x32, K=1536, BK=64 (24 iters), streamed B ----
    for (int it3=0; it3<3; it3++){
      float acc2[2][4];
#pragma unroll
      for (int j=0;j<2;j++)
#pragma unroll
        for (int e=0;e<4;e++) acc2[j][e]=0.f;
      int n0 = cb*96 + it3*32;
      uint4 pa0, pa1, pb;
      { const __nv_bfloat16* p = Apg + (size_t)(t>>2)*G3_ + (t&3)*16;
        pa0 = *(const uint4*)p; pa1 = *(const uint4*)(p+8);
        pb = *(const uint4*)(g_Bp + (size_t)(t>>2)*G3_ + n0 + (t&3)*8); }
      int buf = 0;
      for (int c=0;c<24;c++,buf^=1){
        __nv_bfloat16* Ab = As + buf*(64*136);
        __nv_bfloat16* Bb = Bs + buf*(64*40);
        { __nv_bfloat16* d = Ab + (t>>2)*72 + (t&3)*16;
          *(uint4*)d = pa0; *(uint4*)(d+8) = pa1; }
        *(uint4*)(Bb + (t>>2)*40 + (t&3)*8) = pb;
        __syncthreads();
        if (c<23){
          const __nv_bfloat16* p = Apg + (size_t)(t>>2)*G3_ + (c+1)*64 + (t&3)*16;
          pa0 = *(const uint4*)p; pa1 = *(const uint4*)(p+8);
          pb = *(const uint4*)(g_Bp + (size_t)((c+1)*64 + (t>>2))*G3_ + n0 + (t&3)*8);
        }
#pragma unroll
        for (int kk=0;kk<64;kk+=16){
          unsigned af[4];
          ldsm4(af, Ab + (wm+(lane&15))*72 + kk + ((lane>>4)<<3));
          unsigned bfr[4];
          ldsm4t(bfr, Bb + (kk+l8+((gq&1)<<3))*40 + ((w&1)<<4) + ((gq>>1)<<3));
#pragma unroll
          for (int h2=0;h2<2;h2++){
            unsigned bb[2] = { bfr[h2*2], bfr[h2*2+1] };
            mma_bf16(acc2[h2], af, bb);
          }
        }
      }
      const int wn = (w&1)*16;
#pragma unroll
      for (int tn=0;tn<2;tn++){
        int ccg = n0 + wn + tn*8 + qc*2;
#pragma unroll
        for (int rh=0;rh<2;rh++){
          int rrg = g*64 + wm + qr + rh*8;
          *(float2*)(g_gh + (size_t)rrg*G3_ + ccg) =
              make_float2(acc2[tn][rh*2+0], acc2[tn][rh*2+1]);
        }
      }
    }
    gbar(barc, gen);
    { // ---- GRU + LayerNorm ----
      int b = g*64 + cb*4 + (w>>1);
      int half = w&1;
      const float* gi = g_gi + ((size_t)b*S_ + s)*G3_;
      const float* gh = g_gh + (size_t)b*G3_;
      float v[8]; float lsum = 0.f;
#pragma unroll
      for (int jj=0;jj<8;jj++){
        int j = half*256 + lane + jj*32;
        float rg = 1.f/(1.f+expf(-(gi[j]      + bih[j]      + gh[j]      + bhh[j])));
        float zg = 1.f/(1.f+expf(-(gi[j+H_]   + bih[j+H_]   + gh[j+H_]   + bhh[j+H_])));
        float ng = tanhf(gi[j+2*H_] + bih[j+2*H_] + rg*(gh[j+2*H_] + bhh[j+2*H_]));
        float hv = (1.f - zg)*ng + zg*g_h[(size_t)b*H_+j];
        v[jj] = hv; lsum += hv;
      }
#pragma unroll
      for (int jj=0;jj<8;jj++){
        int j = half*256 + lane + jj*32; float hv = v[jj];
        g_h[(size_t)b*H_+j] = hv;
        g_S[(size_t)b*H_+j] = __float2bfloat16(hv);
        __nv_bfloat16 hi = __float2bfloat16(hv);
        __nv_bfloat16 lo = __float2bfloat16(hv - __bfloat162float(hi));
        g_Ap[(size_t)b*G3_ + j]        = hi;
        g_Ap[(size_t)b*G3_ + H_ + j]   = lo;
        g_Ap[(size_t)b*G3_ + 2*H_ + j] = hi;
      }
#pragma unroll
      for (int o=16;o>0;o>>=1) lsum += __shfl_xor_sync(0xffffffffu, lsum, o);
      if (lane==0) red2[w] = lsum;
      __syncthreads();
      float mu = (red2[w & ~1] + red2[w | 1]) / 512.f;
      float lvar = 0.f;
#pragma unroll
      for (int jj=0;jj<8;jj++){ float d = v[jj]-mu; lvar += d*d; }
#pragma unroll
      for (int o=16;o>0;o>>=1) lvar += __shfl_xor_sync(0xffffffffu, lvar, o);
      if (lane==0) red2[8+w] = lvar;
      __syncthreads();
      float inv = rsqrtf((red2[8+(w & ~1)] + red2[8+(w | 1)])/512.f + 1e-5f);
      float* op = out + ((size_t)b*S_ + s)*H_;
#pragma unroll
      for (int jj=0;jj<8;jj++){
        int j = half*256 + lane + jj*32;
        op[j] = (v[jj]-mu)*inv*gamma[j] + beta[j];
      }
    }
    gbar(barc, gen);
  }
}

// ---------------- one-time gi GEMM (64x64 tile, 128 thr) ----------------
__global__ void __launch_bounds__(128) k_gi(){
  __shared__ __nv_bfloat16 As[64*40];
  __shared__ __nv_bfloat16 Bsl[32*72];
  const int t = threadIdx.x;
  const int m0 = blockIdx.y*64, n0 = blockIdx.x*64;
  const int lane = t&31, w = t>>5;
  const int wm = (w>>1)*32, wn = (w&1)*32;
  const int qr = lane>>2, qc = lane&3;
  float acc[2][4][4];
#pragma unroll
  for (int i=0;i<2;i++)
#pragma unroll
    for (int j=0;j<4;j++)
#pragma unroll
      for (int e=0;e<4;e++) acc[i][j][e]=0.f;
  uint4 pa[2], pb[2];
#pragma unroll
  for (int i=0;i<2;i++){
    int cI = t + i*128;
    pa[i] = *(const uint4*)(g_Ax + (size_t)(m0 + (cI>>2))*KAUG + (cI&3)*8);
    pb[i] = *(const uint4*)(g_Bx + (size_t)(cI>>3)*G3_ + n0 + (cI&7)*8);
  }
  for (int k0=0; k0<KAUG; k0+=32){
#pragma unroll
    for (int i=0;i<2;i++){
      int cI = t + i*128;
      *(uint4*)(As + (cI>>2)*40 + (cI&3)*8) = pa[i];
      *(uint4*)(Bsl + (cI>>3)*72 + (cI&7)*8) = pb[i];
    }
    __syncthreads();
    if (k0+32 < KAUG){
#pragma unroll
      for (int i=0;i<2;i++){
        int cI = t + i*128;
        pa[i] = *(const uint4*)(g_Ax + (size_t)(m0 + (cI>>2))*KAUG + (k0+32) + (cI&3)*8);
        pb[i] = *(const uint4*)(g_Bx + (size_t)(k0+32 + (cI>>3))*G3_ + n0 + (cI&7)*8);
      }
    }
    int l8 = lane&7, gq = lane>>3;
#pragma unroll
    for (int kk=0; kk<32; kk+=16){
      unsigned af[2][4];
#pragma unroll
      for (int tm=0;tm<2;tm++)
        ldsm4(af[tm], As + (wm+tm*16+(lane&15))*40 + kk + ((lane>>4)<<3));
#pragma unroll
      for (int tn2=0; tn2<2; tn2++){
        unsigned bfr[4];
        ldsm4t(bfr, Bsl + (kk+l8+((gq&1)<<3))*72 + wn + tn2*16 + ((gq>>1)<<3));
#pragma unroll
        for (int tm=0;tm<2;tm++)
#pragma unroll
          for (int h2=0; h2<2; h2++){
            unsigned bb[2] = { bfr[h2*2], bfr[h2*2+1] };
            mma_bf16(acc[tm][tn2*2+h2], af[tm], bb);
          }
      }
    }
    __syncthreads();
  }
#pragma unroll
  for (int tm=0;tm<2;tm++)
#pragma unroll
    for (int tn=0;tn<4;tn++){
      int r0 = m0 + wm + tm*16 + qr;
      int c0 = n0 + wn + tn*8 + qc*2;
#pragma unroll
      for (int e=0;e<4;e++){
        int rr = r0 + (e>>1)*8, cc = c0 + (e&1);
        g_gi[(size_t)rr*G3_ + cc] = acc[tm][tn][e];
      }
    }
}

// ---------------- host ----------------
extern "C" void kernel_launch(void* const* d_in, const int* in_sizes, int n_in,
                              void* d_out, int out_size){
  const float* tp    = (const float*)d_in[0];
  const float* vals  = (const float*)d_in[1];
  const float* w1    = (const float*)d_in[2];
  const float* b1    = (const float*)d_in[3];
  const float* w2    = (const float*)d_in[4];
  const float* b2    = (const float*)d_in[5];
  const float* wih   = (const float*)d_in[6];
  const float* whh   = (const float*)d_in[7];
  const float* bih   = (const float*)d_in[8];
  const float* bhh   = (const float*)d_in[9];
  const float* gamma = (const float*)d_in[10];
  const float* beta  = (const float*)d_in[11];
  float* out = (float*)d_out;
  (void)in_sizes; (void)n_in; (void)out_size;

  const int SMEM = 512*72*2 + 1024*40*2 + 2*64*136*2 + 2*64*40*2; // 200704 B
  cudaFuncSetAttribute(k_scan, cudaFuncAttributeMaxDynamicSharedMemorySize, SMEM);

  {
    size_t n = (size_t)B_*S_*KAUG;
    k_pre<<<(unsigned)((n+255)/256),256>>>(tp, vals, w1, w2, whh, wih);
  }
  k_gi<<<dim3(G3_/64,(B_*S_)/64),128>>>();
  k_scan<<<128,256,SMEM>>>(b1,b2,bih,bhh,gamma,beta,out);
}